// round 16
// baseline (speedup 1.0000x reference)
#include <cuda_runtime.h>
#include <cuda_fp16.h>

// WaterLevelLSTM via mma.sync.m16n8k16 (f16->f32), single-term fp16 h,
// persistent CTAs, operand flip (W in registers). R16: four tiles per
// iteration processed as TWO PAIRS with explicitly interleaved instruction
// streams (ldsm / MMA-chains / epilogues alternate between the pair's
// tiles) so in-order warps always have an independent op to issue while
// the sibling tile's chain is stalled.

#define TSTEPS 5
#define NTH    256
#define NBATCH 32
#define NTILE  4
#define HROW   72          // halves per staged row (144 B, conflict-free)

// smem byte offsets
#define SM_WST  0          // permuted W fp16 [256][72] = 36864; dead after
                           // prologue -> aliased by final-h fp32 [4][32][68]
#define SM_H    36864      // h fp16: 4 tiles x 2 bufs x 4608 = 36864
#define SM_XT   73728      // x transposed [4][5][32] floats = 2560
#define SM_WFC  76288      // 64 floats
#define SM_SIZE 76544

typedef unsigned int u32;

__device__ __forceinline__ void mma16816(float* d, const u32* a, const u32* b) {
    asm volatile("mma.sync.aligned.m16n8k16.row.col.f32.f16.f16.f32 "
        "{%0,%1,%2,%3}, {%4,%5,%6,%7}, {%8,%9}, {%0,%1,%2,%3};"
        : "+f"(d[0]), "+f"(d[1]), "+f"(d[2]), "+f"(d[3])
        : "r"(a[0]), "r"(a[1]), "r"(a[2]), "r"(a[3]), "r"(b[0]), "r"(b[1]));
}
__device__ __forceinline__ void mma16816_zc(float* d, const u32* a, const u32* b) {
    asm volatile("mma.sync.aligned.m16n8k16.row.col.f32.f16.f16.f32 "
        "{%0,%1,%2,%3}, {%4,%5,%6,%7}, {%8,%9}, {%10,%11,%12,%13};"
        : "=f"(d[0]), "=f"(d[1]), "=f"(d[2]), "=f"(d[3])
        : "r"(a[0]), "r"(a[1]), "r"(a[2]), "r"(a[3]), "r"(b[0]), "r"(b[1]),
          "f"(0.0f), "f"(0.0f), "f"(0.0f), "f"(0.0f));
}
__device__ __forceinline__ void ldsm4(u32* r, u32 addr) {
    asm volatile("ldmatrix.sync.aligned.m8n8.x4.shared.b16 {%0,%1,%2,%3}, [%4];"
        : "=r"(r[0]), "=r"(r[1]), "=r"(r[2]), "=r"(r[3]) : "r"(addr));
}
__device__ __forceinline__ u32 s2u(const void* p) {
    u32 a;
    asm("{ .reg .u64 t; cvta.to.shared.u64 t, %1; cvt.u32.u64 %0, t; }"
        : "=r"(a) : "l"(p));
    return a;
}
// hardware tanh (MUFU.TANH): 1 MUFU op
__device__ __forceinline__ float tanh_hw(float x) {
    float r;
    asm("tanh.approx.f32 %0, %1;" : "=f"(r) : "f"(x));
    return r;
}
__device__ __forceinline__ float sigf(float x) {
    return fmaf(tanh_hw(0.5f * x), 0.5f, 0.5f);
}

__global__ __launch_bounds__(NTH, 2)
void lstm_mma_kernel(const float* __restrict__ x,
                     const float* __restrict__ W_ih,
                     const float* __restrict__ W_hh,
                     const float* __restrict__ b_ih,
                     const float* __restrict__ b_hh,
                     const float* __restrict__ W_fc,
                     const float* __restrict__ b_fc,
                     float* __restrict__ out,
                     int B, int ngroups)
{
    extern __shared__ char smem[];
    const u32 sb = s2u(smem);
    const int tid  = threadIdx.x;
    const int warp = tid >> 5;
    const int lane = tid & 31;
    const int gid  = lane >> 2;      // hidden-unit row group
    const int tig  = lane & 3;       // batch col group

    __half* wst   = reinterpret_cast<__half*>(smem + SM_WST);
    float*  hf32  = reinterpret_cast<float*>(smem + SM_WST);  // alias post-prologue
    __half* h_s   = reinterpret_cast<__half*>(smem + SM_H);   // [tt][buf][n][HROW]
    float*  xt    = reinterpret_cast<float*>(smem + SM_XT);   // [tt][s][n]
    float*  wfc_s = reinterpret_cast<float*>(smem + SM_WFC);

    // ---- one-time prologue: stage W_hh fp16 with gate-row permutation ----
    for (int i = tid; i < 256 * 64; i += NTH) {
        int n = i >> 6, k = i & 63;
        int type = n >> 6, j = n & 63;
        int prow = 32 * (j >> 3) + 16 * (type >> 1) + 8 * (type & 1) + (j & 7);
        wst[prow * HROW + k] = __float2half_rn(W_hh[i]);
    }
    if (tid < 64) wfc_s[tid] = W_fc[tid];
    __syncthreads();

    // A fragments: this warp's 32 W rows, registers for the whole kernel
    const u32 lmA = (u32)((lane & 15) * (HROW * 2) + (lane >> 4) * 16);
    u32 A[2][4][4];
#pragma unroll
    for (int mt = 0; mt < 2; mt++)
#pragma unroll
        for (int kc = 0; kc < 4; kc++)
            ldsm4(A[mt][kc],
                  sb + SM_WST + (u32)((32 * warp + 16 * mt) * (HROW * 2) + kc * 32) + lmA);

    // per-thread constants: unit j = 8*warp + gid
    const int j = warp * 8 + gid;
    float biasv[4], wihv[4];
#pragma unroll
    for (int t = 0; t < 4; t++) {
        biasv[t] = b_ih[t * 64 + j] + b_hh[t * 64 + j];
        wihv[t]  = W_ih[t * 64 + j];
    }
    const float bfc = b_fc[0];

    const u32 hb0 = sb + SM_H;
    const u32 lmB = (u32)((lane & 7) * (HROW * 2) + (lane >> 3) * 16);

    __syncthreads();   // all A-ldsm done before wst region is aliased by hf32

    // ============ persistent loop: four batch tiles per iteration ============
    for (int grp = blockIdx.x; grp < ngroups; grp += gridDim.x) {
        for (int i = tid; i < NTILE * NBATCH * TSTEPS; i += NTH) {
            int tt = i / (NBATCH * TSTEPS);
            int r  = i % (NBATCH * TSTEPS);
            int n = r / TSTEPS, s = r % TSTEPS;
            long gb = ((long)grp * NTILE + tt) * NBATCH + n;
            xt[tt * 160 + s * NBATCH + n] = (gb < B) ? x[gb * TSTEPS + s] : 0.0f;
        }
        __syncthreads();

        float c[NTILE][8];
#pragma unroll
        for (int tt = 0; tt < NTILE; tt++)
#pragma unroll
            for (int i = 0; i < 8; i++) c[tt][i] = 0.0f;

#pragma unroll
        for (int s = 0; s < TSTEPS; s++) {
#pragma unroll
            for (int pp = 0; pp < 2; pp++) {
                const int t0 = pp * 2, t1 = pp * 2 + 1;
                const u32 hrd0 = hb0 + (u32)(t0 * 9216 + ((s & 1) ^ 1) * 4608);
                const u32 hrd1 = hb0 + (u32)(t1 * 9216 + ((s & 1) ^ 1) * 4608);
                __half* hw0 = h_s + t0 * 4608 + (s & 1) * 2304;
                __half* hw1 = h_s + t1 * 4608 + (s & 1) * 2304;
                const float* xts0 = xt + t0 * 160 + s * NBATCH;
                const float* xts1 = xt + t1 * 160 + s * NBATCH;

#pragma unroll
                for (int ng = 0; ng < 4; ng++) {
                    u32 Bf0[8], Bf1[8];
                    float D0[2][4], D1[2][4];
                    if (s > 0) {
                        const u32 o = (u32)(ng * 8 * (HROW * 2)) + lmB;
                        // interleaved ldsm: 4 independent LDS in flight
                        ldsm4(Bf0 + 0, hrd0 + o);
                        ldsm4(Bf1 + 0, hrd1 + o);
                        ldsm4(Bf0 + 4, hrd0 + o + 64);
                        ldsm4(Bf1 + 4, hrd1 + o + 64);
                        // 4 MMA chains advance in parallel (kk-major order)
                        mma16816_zc(D0[0], A[0][0], Bf0 + 0);
                        mma16816_zc(D1[0], A[0][0], Bf1 + 0);
                        mma16816_zc(D0[1], A[1][0], Bf0 + 0);
                        mma16816_zc(D1[1], A[1][0], Bf1 + 0);
#pragma unroll
                        for (int kk = 1; kk < 4; kk++) {
                            mma16816(D0[0], A[0][kk], Bf0 + 2 * kk);
                            mma16816(D1[0], A[0][kk], Bf1 + 2 * kk);
                            mma16816(D0[1], A[1][kk], Bf0 + 2 * kk);
                            mma16816(D1[1], A[1][kk], Bf1 + 2 * kk);
                        }
                    }

                    float2 xp0 = *(const float2*)(xts0 + ng * 8 + 2 * tig);
                    float2 xp1 = *(const float2*)(xts1 + ng * 8 + 2 * tig);
                    // epilogues interleaved: (b, tile) pairs alternate
#pragma unroll
                    for (int b = 0; b < 2; b++) {
#pragma unroll
                        for (int t = 0; t < 2; t++) {
                            const float xv = t ? (b ? xp1.y : xp1.x)
                                               : (b ? xp0.y : xp0.x);
                            const float* Dv = t ? &D1[0][0] : &D0[0][0];
                            const int tt = t ? t1 : t0;
                            float gI = fmaf(xv, wihv[0], biasv[0]);
                            float gF = fmaf(xv, wihv[1], biasv[1]);
                            float gG = fmaf(xv, wihv[2], biasv[2]);
                            float gO = fmaf(xv, wihv[3], biasv[3]);
                            if (s > 0) {
                                gI += Dv[b];          // D[0][b]
                                gF += Dv[2 + b];      // D[0][2+b]
                                gG += Dv[4 + b];      // D[1][b]
                                gO += Dv[6 + b];      // D[1][2+b]
                            }
                            float iv = sigf(gI);
                            float fv = sigf(gF);
                            float gv = tanh_hw(gG);
                            float ov = sigf(gO);
                            float cn = fmaf(fv, c[tt][ng * 2 + b], iv * gv);
                            c[tt][ng * 2 + b] = cn;
                            float h = ov * tanh_hw(cn);
                            const int n = ng * 8 + 2 * tig + b;
                            __half* hw = t ? hw1 : hw0;
                            if (s < TSTEPS - 1) {
                                hw[n * HROW + j] = __float2half_rn(h);
                            } else {
                                hf32[tt * 2176 + n * 68 + j] = h;
                            }
                        }
                    }
                }
            }
            __syncthreads();   // all tiles' h complete before next step
        }

        // ---- head: 8 threads per batch row, shfl-tree reduce, all tiles ----
#pragma unroll
        for (int tt = 0; tt < NTILE; tt++) {
            const int n    = tid >> 3;
            const int part = tid & 7;
            float acc = 0.0f;
#pragma unroll
            for (int q = 0; q < 8; q++) {
                int jj = part * 8 + q;
                acc = fmaf(hf32[tt * 2176 + n * 68 + jj], wfc_s[jj], acc);
            }
            acc += __shfl_xor_sync(0xffffffffu, acc, 1);
            acc += __shfl_xor_sync(0xffffffffu, acc, 2);
            acc += __shfl_xor_sync(0xffffffffu, acc, 4);
            if (part == 0) {
                long g = ((long)grp * NTILE + tt) * NBATCH + n;
                if (g < B) out[g] = acc + bfc;
            }
        }
        __syncthreads();   // hf32/xt reads done before next group overwrites
    }
}

extern "C" void kernel_launch(void* const* d_in, const int* in_sizes, int n_in,
                              void* d_out, int out_size) {
    const float* x    = (const float*)d_in[0];
    const float* W_ih = (const float*)d_in[1];
    const float* W_hh = (const float*)d_in[2];
    const float* b_ih = (const float*)d_in[3];
    const float* b_hh = (const float*)d_in[4];
    const float* W_fc = (const float*)d_in[5];
    const float* b_fc = (const float*)d_in[6];
    float* out = (float*)d_out;

    const int B = in_sizes[0] / TSTEPS;
    const int ntiles  = (B + NBATCH - 1) / NBATCH;
    const int ngroups = (ntiles + NTILE - 1) / NTILE;
    int grid = 296;                       // 2 CTAs x 148 SMs, persistent
    if (ngroups < grid) grid = ngroups;

    cudaFuncSetAttribute(lstm_mma_kernel,
                         cudaFuncAttributeMaxDynamicSharedMemorySize, SM_SIZE);
    lstm_mma_kernel<<<grid, NTH, SM_SIZE>>>(x, W_ih, W_hh, b_ih, b_hh,
                                            W_fc, b_fc, out, B, ngroups);
}

// round 17
// speedup vs baseline: 1.0817x; 1.0817x over previous
#include <cuda_runtime.h>
#include <cuda_fp16.h>

// WaterLevelLSTM via mma.sync.m16n8k16 (f16->f32), single-term fp16 h,
// persistent CTAs, operand flip (W in registers). R17 = R14 two-tile
// kernel at 3 CTAs/SM (24 warps) for +50% latency hiding: smem trimmed to
// 56.8KB/CTA, regs capped at 84 via launch_bounds(256,3).

#define TSTEPS 5
#define NTH    256
#define NBATCH 32
#define HROW   72          // halves per staged row (144 B, conflict-free)

// smem byte offsets
#define SM_WST  0          // permuted W fp16 [256][72] = 36864; dead after
                           // prologue -> aliased by final-h fp32 [2][32][68]
#define SM_H    36864      // h fp16: 2 tiles x 2 bufs x 4608 = 18432
#define SM_XT   55296      // x transposed [2][5][32] floats = 1280
#define SM_WFC  56576      // 64 floats
#define SM_SIZE 56832

typedef unsigned int u32;

__device__ __forceinline__ void mma16816(float* d, const u32* a, const u32* b) {
    asm volatile("mma.sync.aligned.m16n8k16.row.col.f32.f16.f16.f32 "
        "{%0,%1,%2,%3}, {%4,%5,%6,%7}, {%8,%9}, {%0,%1,%2,%3};"
        : "+f"(d[0]), "+f"(d[1]), "+f"(d[2]), "+f"(d[3])
        : "r"(a[0]), "r"(a[1]), "r"(a[2]), "r"(a[3]), "r"(b[0]), "r"(b[1]));
}
__device__ __forceinline__ void mma16816_zc(float* d, const u32* a, const u32* b) {
    asm volatile("mma.sync.aligned.m16n8k16.row.col.f32.f16.f16.f32 "
        "{%0,%1,%2,%3}, {%4,%5,%6,%7}, {%8,%9}, {%10,%11,%12,%13};"
        : "=f"(d[0]), "=f"(d[1]), "=f"(d[2]), "=f"(d[3])
        : "r"(a[0]), "r"(a[1]), "r"(a[2]), "r"(a[3]), "r"(b[0]), "r"(b[1]),
          "f"(0.0f), "f"(0.0f), "f"(0.0f), "f"(0.0f));
}
__device__ __forceinline__ void ldsm4(u32* r, u32 addr) {
    asm volatile("ldmatrix.sync.aligned.m8n8.x4.shared.b16 {%0,%1,%2,%3}, [%4];"
        : "=r"(r[0]), "=r"(r[1]), "=r"(r[2]), "=r"(r[3]) : "r"(addr));
}
__device__ __forceinline__ u32 s2u(const void* p) {
    u32 a;
    asm("{ .reg .u64 t; cvta.to.shared.u64 t, %1; cvt.u32.u64 %0, t; }"
        : "=r"(a) : "l"(p));
    return a;
}
// hardware tanh (MUFU.TANH): 1 MUFU op
__device__ __forceinline__ float tanh_hw(float x) {
    float r;
    asm("tanh.approx.f32 %0, %1;" : "=f"(r) : "f"(x));
    return r;
}
__device__ __forceinline__ float sigf(float x) {
    return fmaf(tanh_hw(0.5f * x), 0.5f, 0.5f);
}

__global__ __launch_bounds__(NTH, 3)
void lstm_mma_kernel(const float* __restrict__ x,
                     const float* __restrict__ W_ih,
                     const float* __restrict__ W_hh,
                     const float* __restrict__ b_ih,
                     const float* __restrict__ b_hh,
                     const float* __restrict__ W_fc,
                     const float* __restrict__ b_fc,
                     float* __restrict__ out,
                     int B, int npairs)
{
    extern __shared__ char smem[];
    const u32 sb = s2u(smem);
    const int tid  = threadIdx.x;
    const int warp = tid >> 5;
    const int lane = tid & 31;
    const int gid  = lane >> 2;      // hidden-unit row group
    const int tig  = lane & 3;       // batch col group

    __half* wst   = reinterpret_cast<__half*>(smem + SM_WST);
    float*  hf32  = reinterpret_cast<float*>(smem + SM_WST);  // alias post-prologue
    __half* h_s   = reinterpret_cast<__half*>(smem + SM_H);   // [tt][buf][n][HROW]
    float*  xt    = reinterpret_cast<float*>(smem + SM_XT);   // [tt][s][n]
    float*  wfc_s = reinterpret_cast<float*>(smem + SM_WFC);

    // ---- one-time prologue: stage W_hh fp16 with gate-row permutation ----
    // prow(type,j) = 32*(j>>3) + 16*(type>>1) + 8*(type&1) + (j&7)
    for (int i = tid; i < 256 * 64; i += NTH) {
        int n = i >> 6, k = i & 63;
        int type = n >> 6, j = n & 63;
        int prow = 32 * (j >> 3) + 16 * (type >> 1) + 8 * (type & 1) + (j & 7);
        wst[prow * HROW + k] = __float2half_rn(W_hh[i]);
    }
    if (tid < 64) wfc_s[tid] = W_fc[tid];
    __syncthreads();

    // A fragments: this warp's 32 W rows, registers for the whole kernel
    const u32 lmA = (u32)((lane & 15) * (HROW * 2) + (lane >> 4) * 16);
    u32 A[2][4][4];
#pragma unroll
    for (int mt = 0; mt < 2; mt++)
#pragma unroll
        for (int kc = 0; kc < 4; kc++)
            ldsm4(A[mt][kc],
                  sb + SM_WST + (u32)((32 * warp + 16 * mt) * (HROW * 2) + kc * 32) + lmA);

    // per-thread constants: unit j = 8*warp + gid
    const int j = warp * 8 + gid;
    float biasv[4], wihv[4];
#pragma unroll
    for (int t = 0; t < 4; t++) {
        biasv[t] = b_ih[t * 64 + j] + b_hh[t * 64 + j];
        wihv[t]  = W_ih[t * 64 + j];
    }
    const float bfc = b_fc[0];

    const u32 hb0 = sb + SM_H;
    const u32 lmB = (u32)((lane & 7) * (HROW * 2) + (lane >> 3) * 16);

    __syncthreads();   // all A-ldsm done before wst region is aliased by hf32

    // ============ persistent loop: two batch tiles per iteration ============
    for (int pair = blockIdx.x; pair < npairs; pair += gridDim.x) {
        // stage x transposed [tt][s][n]
        for (int i = tid; i < 2 * NBATCH * TSTEPS; i += NTH) {
            int tt = i / (NBATCH * TSTEPS);
            int r  = i % (NBATCH * TSTEPS);
            int n = r / TSTEPS, s = r % TSTEPS;
            long gb = ((long)pair * 2 + tt) * NBATCH + n;
            xt[tt * 160 + s * NBATCH + n] = (gb < B) ? x[gb * TSTEPS + s] : 0.0f;
        }
        __syncthreads();

        float c[2][8];
#pragma unroll
        for (int tt = 0; tt < 2; tt++)
#pragma unroll
            for (int i = 0; i < 8; i++) c[tt][i] = 0.0f;

#pragma unroll
        for (int s = 0; s < TSTEPS; s++) {
#pragma unroll
            for (int tt = 0; tt < 2; tt++) {
                const u32 hrd = hb0 + (u32)(tt * 9216 + ((s & 1) ^ 1) * 4608);
                __half* hw = h_s + tt * 4608 + (s & 1) * 2304;   // halves
                const float* xts = xt + tt * 160 + s * NBATCH;

#pragma unroll
                for (int ng = 0; ng < 4; ng++) {
                    u32 Bf[8];
                    float D[2][4];
                    if (s > 0) {
                        ldsm4(Bf + 0, hrd + (u32)(ng * 8 * (HROW * 2)) + lmB);
                        ldsm4(Bf + 4, hrd + (u32)(ng * 8 * (HROW * 2) + 64) + lmB);
#pragma unroll
                        for (int mt = 0; mt < 2; mt++) {
                            mma16816_zc(D[mt], A[mt][0], Bf + 0);
#pragma unroll
                            for (int kk = 1; kk < 4; kk++)
                                mma16816(D[mt], A[mt][kk], Bf + 2 * kk);
                        }
                    }

                    float2 xp = *(const float2*)(xts + ng * 8 + 2 * tig);
#pragma unroll
                    for (int b = 0; b < 2; b++) {
                        const float xv = b ? xp.y : xp.x;
                        float gI = fmaf(xv, wihv[0], biasv[0]);
                        float gF = fmaf(xv, wihv[1], biasv[1]);
                        float gG = fmaf(xv, wihv[2], biasv[2]);
                        float gO = fmaf(xv, wihv[3], biasv[3]);
                        if (s > 0) {
                            gI += D[0][b];
                            gF += D[0][2 + b];
                            gG += D[1][b];
                            gO += D[1][2 + b];
                        }
                        float iv = sigf(gI);
                        float fv = sigf(gF);
                        float gv = tanh_hw(gG);
                        float ov = sigf(gO);
                        float cn = fmaf(fv, c[tt][ng * 2 + b], iv * gv);
                        c[tt][ng * 2 + b] = cn;
                        float h = ov * tanh_hw(cn);
                        const int n = ng * 8 + 2 * tig + b;
                        if (s < TSTEPS - 1) {
                            hw[n * HROW + j] = __float2half_rn(h);   // STS.16
                        } else {
                            hf32[tt * 2176 + n * 68 + j] = h;        // exact head in
                        }
                    }
                }
            }
            __syncthreads();   // both tiles' h complete before next step
        }

        // ---- head: 8 threads per batch row, shfl-tree reduce, both tiles ----
#pragma unroll
        for (int tt = 0; tt < 2; tt++) {
            const int n    = tid >> 3;
            const int part = tid & 7;
            float acc = 0.0f;
#pragma unroll
            for (int q = 0; q < 8; q++) {
                int jj = part * 8 + q;
                acc = fmaf(hf32[tt * 2176 + n * 68 + jj], wfc_s[jj], acc);
            }
            acc += __shfl_xor_sync(0xffffffffu, acc, 1);
            acc += __shfl_xor_sync(0xffffffffu, acc, 2);
            acc += __shfl_xor_sync(0xffffffffu, acc, 4);
            if (part == 0) {
                long g = ((long)pair * 2 + tt) * NBATCH + n;
                if (g < B) out[g] = acc + bfc;
            }
        }
        __syncthreads();   // hf32/xt reads done before next pair overwrites
    }
}

extern "C" void kernel_launch(void* const* d_in, const int* in_sizes, int n_in,
                              void* d_out, int out_size) {
    const float* x    = (const float*)d_in[0];
    const float* W_ih = (const float*)d_in[1];
    const float* W_hh = (const float*)d_in[2];
    const float* b_ih = (const float*)d_in[3];
    const float* b_hh = (const float*)d_in[4];
    const float* W_fc = (const float*)d_in[5];
    const float* b_fc = (const float*)d_in[6];
    float* out = (float*)d_out;

    const int B = in_sizes[0] / TSTEPS;
    const int ntiles = (B + NBATCH - 1) / NBATCH;
    const int npairs = (ntiles + 1) / 2;
    int grid = 444;                       // 3 CTAs x 148 SMs, persistent
    if (npairs < grid) grid = npairs;

    cudaFuncSetAttribute(lstm_mma_kernel,
                         cudaFuncAttributeMaxDynamicSharedMemorySize, SM_SIZE);
    lstm_mma_kernel<<<grid, NTH, SM_SIZE>>>(x, W_ih, W_hh, b_ih, b_hh,
                                            W_fc, b_fc, out, B, npairs);
}